// round 11
// baseline (speedup 1.0000x reference)
#include <cuda_runtime.h>
#include <cuda_bf16.h>
#include <math.h>
#include <stdint.h>

// Problem constants
#define NROWS 16384
#define NE    16384
#define D     256
#define HW    1024
#define CHW   262144

#define NT       128        // number of 128-code tiles
#define MARGIN_M 2e-4f      // margin on m_hat (provable bound ~9.6e-5)

// Output layout (concatenated reference tuple, float32)
#define ZQ_OFF   0ULL
#define LOSS_OFF 4194304ULL
#define PERP_OFF 4194305ULL
#define OH_OFF   4194306ULL
#define IDX_OFF  272629762ULL

// Scratch
__device__ float  g_enorm[NE];
__device__ int    g_idx[NROWS];
__device__ int    g_count[NE];
__device__ double g_losspart[16384];
__device__ uint4  g_ebf8[NE * 32];              // bf16 codebook, tile-major + swizzled (8 MB)
__device__ float  g_smax[(size_t)NROWS * 1024]; // per-row per-16-code-subtile max(m_hat)

// ---------------------------------------------------------------------------
// Baseline-PTX helpers (sm_90 features only)
// ---------------------------------------------------------------------------
__device__ __forceinline__ uint32_t smem_to_u32(const void* p) {
    uint32_t a;
    asm("{ .reg .u64 t; cvta.to.shared.u64 t, %1; cvt.u32.u64 %0, t; }" : "=r"(a) : "l"(p));
    return a;
}
#define MBARRIER_INIT(mb, cnt) \
    asm volatile("mbarrier.init.shared.b64 [%0], %1;" :: "r"((uint32_t)(mb)), "r"((uint32_t)(cnt)) : "memory")
#define MBARRIER_EXPECT_TX(mb, bytes) \
    asm volatile("mbarrier.arrive.expect_tx.shared.b64 _, [%0], %1;" :: "r"((uint32_t)(mb)), "r"((uint32_t)(bytes)) : "memory")
#define MBARRIER_WAIT_PARITY(mb, ph) do {                                          \
    uint32_t _m = (uint32_t)(mb); uint32_t _p = (uint32_t)(ph); uint32_t _d;       \
    asm volatile("{\n\t.reg .pred p;\n\t"                                          \
        "mbarrier.try_wait.parity.shared.b64 p, [%1], %2;\n\t"                     \
        "selp.b32 %0, 1, 0, p;\n\t}" : "=r"(_d) : "r"(_m), "r"(_p) : "memory");    \
    if (!_d) {                                                                     \
        asm volatile("{\n\t.reg .pred P1;\n\tWL_%=:\n\t"                           \
            "mbarrier.try_wait.parity.shared.b64 P1, [%0], %1;\n\t"                \
            "@P1 bra.uni WD_%=;\n\tbra.uni WL_%=;\n\tWD_%=:\n\t}"                  \
            :: "r"(_m), "r"(_p) : "memory");                                       \
    } } while (0)

__device__ __forceinline__ void bulk_g2s(uint32_t dst, const void* src, uint32_t bytes, uint32_t mbar) {
    asm volatile("cp.async.bulk.shared::cluster.global.mbarrier::complete_tx::bytes [%0], [%1], %2, [%3];"
                 :: "r"(dst), "l"(src), "r"(bytes), "r"(mbar) : "memory");
}
__device__ __forceinline__ void ldm_x4(uint32_t* r, uint32_t addr) {
    asm volatile("ldmatrix.sync.aligned.m8n8.x4.shared.b16 {%0,%1,%2,%3}, [%4];"
                 : "=r"(r[0]), "=r"(r[1]), "=r"(r[2]), "=r"(r[3]) : "r"(addr));
}
__device__ __forceinline__ void mma16816(float* c, const uint32_t* a, uint32_t b0, uint32_t b1) {
    asm volatile("mma.sync.aligned.m16n8k16.row.col.f32.bf16.bf16.f32 "
                 "{%0,%1,%2,%3}, {%4,%5,%6,%7}, {%8,%9}, {%0,%1,%2,%3};"
                 : "+f"(c[0]), "+f"(c[1]), "+f"(c[2]), "+f"(c[3])
                 : "r"(a[0]), "r"(a[1]), "r"(a[2]), "r"(a[3]), "r"(b0), "r"(b1));
}

// ---------------------------------------------------------------------------
// Zero-fill (side stream, overlapped with GEMM)
// ---------------------------------------------------------------------------
__global__ void k_zero(float* __restrict__ out, long long total) {
    float4* o4 = (float4*)(out + LOSS_OFF);
    long long n = total - (long long)LOSS_OFF;
    long long n4 = n / 4;
    long long i = (long long)blockIdx.x * blockDim.x + threadIdx.x;
    long long stride = (long long)gridDim.x * blockDim.x;
    float4 zz = make_float4(0.f, 0.f, 0.f, 0.f);
    for (long long p = i; p < n4; p += stride) o4[p] = zz;
    long long t0 = n4 * 4;
    if (i < n - t0) out[LOSS_OFF + t0 + i] = 0.f;
}

__global__ void k_zero_counts() {
    int i = blockIdx.x * blockDim.x + threadIdx.x;
    if (i < NE) g_count[i] = 0;
}

// ---------------------------------------------------------------------------
// Fused e-prep: exact sequential ||e||^2 + bf16 codebook tile-major swizzled
// ---------------------------------------------------------------------------
__global__ void k_eprep(const float* __restrict__ emb) {
    __shared__ float se[32 * 257];
    int r0 = blockIdx.x * 32;
    int tid = threadIdx.x;
    const float* src = emb + (size_t)r0 * D;
    #pragma unroll
    for (int l = 0; l < 32; l++) {
        int i = l * 256 + tid;
        se[(i >> 8) * 257 + (i & 255)] = src[i];
    }
    __syncthreads();
    #pragma unroll
    for (int l = 0; l < 4; l++) {
        int id = l * 256 + tid;              // chunk id: 32 rows x 32 chunks
        int r = id >> 5, c = id & 31;
        int j = r0 + r;
        int tile = j >> 7, n = j & 127;
        const float* s8 = se + r * 257 + c * 8;
        uint32_t w[4];
        #pragma unroll
        for (int q = 0; q < 4; q++) {
            __nv_bfloat16 h0 = __float2bfloat16_rn(s8[q * 2]);
            __nv_bfloat16 h1 = __float2bfloat16_rn(s8[q * 2 + 1]);
            w[q] = (uint32_t)*(unsigned short*)&h0 | ((uint32_t)*(unsigned short*)&h1 << 16);
        }
        g_ebf8[(size_t)tile * 4096 + n * 32 + (c ^ (n & 7))] =
            make_uint4(w[0], w[1], w[2], w[3]);
    }
    if (tid < 32) {
        float s = 0.f;
        const float* row = se + tid * 257;
        for (int k = 0; k < D; k++) s = __fadd_rn(s, __fmul_rn(row[k], row[k]));
        g_enorm[r0 + tid] = s;
    }
}

// ---------------------------------------------------------------------------
// Main kernel: bf16 mma.sync GEMM (single pass, bulk-DMA double buffer,
// per-(row, 16-code subtile) max) + fused znorm + fused exact rescore.
// 128 CTAs x 256 threads (8 warps, 2x4).
// ---------------------------------------------------------------------------
#define A_OFF  0
#define B_OFF  65536
#define B_SZ   65536
#define ST_OFF (B_OFF + 2 * B_SZ)           // 196608: stmax[2][128][9] floats
#define S_OFF  (ST_OFF + 2 * 128 * 9 * 4)   // 205824: S[128]
#define MB_OFF (S_OFF + 512)                // 206336
#define FL_OFF 16384                        // rescore flist (reuses A region)
#define SMEM_BYTES (MB_OFF + 64)            // 206400

__launch_bounds__(256, 1)
__global__ void k_main(const float* __restrict__ z, const float* __restrict__ emb) {
    extern __shared__ char smem[];
    uint32_t sbase = smem_to_u32(smem);
    float* stmax = (float*)(smem + ST_OFF);
    float* sS    = (float*)(smem + S_OFF);
    uint32_t mb0 = sbase + MB_OFF, mb1 = sbase + MB_OFF + 8;

    int tid  = threadIdx.x;
    int lane = tid & 31;
    int wid  = tid >> 5;
    int wm = wid >> 2;
    int wn = wid & 3;
    int row0 = blockIdx.x * 128;
    int b0 = row0 >> 10;
    int hw0 = row0 & 1023;

    if (tid == 0) { MBARRIER_INIT(mb0, 1); MBARRIER_INIT(mb1, 1); }
    __syncthreads();
    if (tid == 0) {
        MBARRIER_EXPECT_TX(mb0, B_SZ);
        bulk_g2s(sbase + B_OFF, g_ebf8, B_SZ, mb0);
        MBARRIER_EXPECT_TX(mb1, B_SZ);
        bulk_g2s(sbase + B_OFF + B_SZ, g_ebf8 + 4096, B_SZ, mb1);
    }

    // ---- Stage A: z -> bf16 smem (swizzled) + exact sequential znorm ----
    if (tid < 128) {
        int m = tid;
        const float* zb = z + (size_t)b0 * CHW + hw0 + m;
        int mx7 = m & 7;
        float s = 0.f;
        #pragma unroll 4
        for (int c = 0; c < 32; c++) {       // 16B chunk = dims c*8..c*8+7
            float v[8];
            #pragma unroll
            for (int q = 0; q < 8; q++) v[q] = zb[(size_t)(c * 8 + q) * HW];
            #pragma unroll
            for (int q = 0; q < 8; q++) s = __fadd_rn(s, __fmul_rn(v[q], v[q]));
            uint32_t w[4];
            #pragma unroll
            for (int q = 0; q < 4; q++) {
                __nv_bfloat16 h0 = __float2bfloat16_rn(v[q * 2]);
                __nv_bfloat16 h1 = __float2bfloat16_rn(v[q * 2 + 1]);
                w[q] = (uint32_t)*(unsigned short*)&h0 | ((uint32_t)*(unsigned short*)&h1 << 16);
            }
            *(uint4*)(smem + A_OFF + m * 512 + ((c ^ mx7) << 4)) =
                make_uint4(w[0], w[1], w[2], w[3]);
        }
        sS[m] = s;
    }
    __syncthreads();

    // =========================== GEMM main loop =============================
    #pragma unroll 1
    for (int t = 0; t < NT; t++) {
        int buf = t & 1;
        MBARRIER_WAIT_PARITY(buf ? mb1 : mb0, (t >> 1) & 1);

        float acc[4][4][4];
        #pragma unroll
        for (int mt = 0; mt < 4; mt++)
            #pragma unroll
            for (int nt = 0; nt < 4; nt++)
                #pragma unroll
                for (int rr = 0; rr < 4; rr++) acc[mt][nt][rr] = 0.f;

        int rA = wm * 64 + (lane & 15);
        int rB = wn * 32 + (lane & 15);
        int hi = lane >> 4;
        uint32_t bB = sbase + B_OFF + (uint32_t)buf * B_SZ;

        #pragma unroll
        for (int ks = 0; ks < 16; ks++) {
            int chunk = ks * 2 + hi;
            uint32_t ra[4][4], rb[2][4];
            #pragma unroll
            for (int mt = 0; mt < 4; mt++) {
                int r = rA + mt * 16;
                ldm_x4(ra[mt], sbase + A_OFF + (uint32_t)(r * 512 + ((chunk ^ (r & 7)) << 4)));
            }
            #pragma unroll
            for (int np = 0; np < 2; np++) {
                int r = rB + np * 16;
                ldm_x4(rb[np], bB + (uint32_t)(r * 512 + ((chunk ^ (r & 7)) << 4)));
            }
            #pragma unroll
            for (int mt = 0; mt < 4; mt++) {
                mma16816(acc[mt][0], ra[mt], rb[0][0], rb[0][2]);
                mma16816(acc[mt][1], ra[mt], rb[0][1], rb[0][3]);
                mma16816(acc[mt][2], ra[mt], rb[1][0], rb[1][2]);
                mma16816(acc[mt][3], ra[mt], rb[1][1], rb[1][3]);
            }
        }

        // ---- Epilogue: per-(row, 16-code subtile) max of m_hat ----
        float* stm = stmax + buf * (128 * 9);
        #pragma unroll
        for (int mt = 0; mt < 4; mt++) {
            int rl = wm * 64 + mt * 16 + (lane >> 2);
            #pragma unroll
            for (int sb = 0; sb < 2; sb++) {
                float m0 = fmaxf(fmaxf(acc[mt][sb*2][0], acc[mt][sb*2][1]),
                                 fmaxf(acc[mt][sb*2+1][0], acc[mt][sb*2+1][1]));
                float m1 = fmaxf(fmaxf(acc[mt][sb*2][2], acc[mt][sb*2][3]),
                                 fmaxf(acc[mt][sb*2+1][2], acc[mt][sb*2+1][3]));
                m0 = fmaxf(m0, __shfl_xor_sync(0xffffffffu, m0, 1));
                m0 = fmaxf(m0, __shfl_xor_sync(0xffffffffu, m0, 2));
                m1 = fmaxf(m1, __shfl_xor_sync(0xffffffffu, m1, 1));
                m1 = fmaxf(m1, __shfl_xor_sync(0xffffffffu, m1, 2));
                if ((lane & 3) == 0) {
                    stm[rl * 9 + wn * 2 + sb]       = m0;
                    stm[(rl + 8) * 9 + wn * 2 + sb] = m1;
                }
            }
        }
        __syncthreads();                     // epilogue written; MMA reads done
        if (tid < 128) {
            const float* s = stm + tid * 9;
            float4* d = (float4*)(g_smax + (size_t)(row0 + tid) * 1024 + t * 8);
            d[0] = make_float4(s[0], s[1], s[2], s[3]);
            d[1] = make_float4(s[4], s[5], s[6], s[7]);
        }
        if (tid == 0 && t + 2 < NT) {
            uint32_t mb = buf ? mb1 : mb0;
            MBARRIER_EXPECT_TX(mb, B_SZ);
            bulk_g2s(sbase + B_OFF + (uint32_t)buf * B_SZ,
                     g_ebf8 + (size_t)(t + 2) * 4096, B_SZ, mb);
        }
    }
    __syncthreads();                         // g_smax complete for this CTA

    // ====================== Fused exact rescore =============================
    // warp wid handles rows wid*16 .. wid*16+15 (local)
    float* zsw   = (float*)(smem) + wid * 256;               // reuse A region
    int*   flist = (int*)(smem + FL_OFF) + wid * 32;
    int*   fcntp = (int*)(smem + FL_OFF + 1024) + wid;

    #pragma unroll 1
    for (int rr8 = 0; rr8 < 16; rr8++) {
        int r = wid * 16 + rr8;
        int w = row0 + r;
        const float* zr = z + (size_t)b0 * CHW + hw0 + r;
        #pragma unroll
        for (int c = lane; c < 256; c += 32) zsw[c] = zr[(size_t)c * HW];
        if (lane == 0) *fcntp = 0;
        __syncwarp();

        const float4* sm4 = (const float4*)(g_smax + (size_t)w * 1024);
        float4 vv[8];
        float mx = -INFINITY;
        #pragma unroll
        for (int i = 0; i < 8; i++) {
            vv[i] = sm4[i * 32 + lane];
            mx = fmaxf(mx, fmaxf(fmaxf(vv[i].x, vv[i].y), fmaxf(vv[i].z, vv[i].w)));
        }
        #pragma unroll
        for (int o = 16; o; o >>= 1) mx = fmaxf(mx, __shfl_xor_sync(0xffffffffu, mx, o));
        float thr = mx - MARGIN_M;

        #pragma unroll
        for (int i = 0; i < 8; i++) {
            int sb = (i * 32 + lane) * 4;
            if (vv[i].x > thr) { int p = atomicAdd(fcntp, 1); if (p < 32) flist[p] = sb; }
            if (vv[i].y > thr) { int p = atomicAdd(fcntp, 1); if (p < 32) flist[p] = sb + 1; }
            if (vv[i].z > thr) { int p = atomicAdd(fcntp, 1); if (p < 32) flist[p] = sb + 2; }
            if (vv[i].w > thr) { int p = atomicAdd(fcntp, 1); if (p < 32) flist[p] = sb + 3; }
        }
        __syncwarp();
        int nf = *fcntp;

        float Sz = sS[r];
        float bestd = INFINITY; int besti = 0x7fffffff;

        if (nf <= 32) {
            for (int base = 0; base < nf; base += 2) {
                int li = base + (lane >> 4);
                float dd = INFINITY; int code = 0x7fffffff;
                if (li < nf) {
                    code = flist[li] * 16 + (lane & 15);
                    const float4* er = (const float4*)(emb + (size_t)code * D);
                    float a = 0.f;
                    #pragma unroll 16
                    for (int q = 0; q < 64; q++) {
                        float4 ev = er[q];
                        a = fmaf(zsw[q * 4],     ev.x, a);
                        a = fmaf(zsw[q * 4 + 1], ev.y, a);
                        a = fmaf(zsw[q * 4 + 2], ev.z, a);
                        a = fmaf(zsw[q * 4 + 3], ev.w, a);
                    }
                    dd = __fadd_rn(__fadd_rn(Sz, g_enorm[code]), __fmul_rn(-2.0f, a));
                }
                if (dd < bestd || (dd == bestd && code < besti)) { bestd = dd; besti = code; }
            }
        } else {
            const float* sm = g_smax + (size_t)w * 1024;
            for (int sb = 0; sb < 1024; sb += 2) {
                int s = sb + (lane >> 4);
                float dd = INFINITY; int code = 0x7fffffff;
                if (sm[s] > thr) {
                    code = s * 16 + (lane & 15);
                    const float4* er = (const float4*)(emb + (size_t)code * D);
                    float a = 0.f;
                    for (int q = 0; q < 64; q++) {
                        float4 ev = er[q];
                        a = fmaf(zsw[q * 4],     ev.x, a);
                        a = fmaf(zsw[q * 4 + 1], ev.y, a);
                        a = fmaf(zsw[q * 4 + 2], ev.z, a);
                        a = fmaf(zsw[q * 4 + 3], ev.w, a);
                    }
                    dd = __fadd_rn(__fadd_rn(Sz, g_enorm[code]), __fmul_rn(-2.0f, a));
                }
                if (dd < bestd || (dd == bestd && code < besti)) { bestd = dd; besti = code; }
            }
        }
        #pragma unroll
        for (int o = 16; o; o >>= 1) {
            float vo = __shfl_xor_sync(0xffffffffu, bestd, o);
            int io = __shfl_xor_sync(0xffffffffu, besti, o);
            if (vo < bestd || (vo == bestd && io < besti)) { bestd = vo; besti = io; }
        }
        if (lane == 0) g_idx[w] = besti;
    }
}

// ---------------------------------------------------------------------------
__global__ void k_finalize(float* __restrict__ out) {
    int r = blockIdx.x * blockDim.x + threadIdx.x;
    if (r >= NROWS) return;
    int idx = g_idx[r];
    out[IDX_OFF + r] = (float)idx;
    out[OH_OFF + (size_t)r * NE + idx] = 1.0f;
    atomicAdd(&g_count[idx], 1);
}

__global__ void k_zq_loss(const float* __restrict__ z, const float* __restrict__ emb,
                          float* __restrict__ out) {
    int t = blockIdx.x * 256 + threadIdx.x;
    int bi = t >> 18;
    int c  = (t >> 10) & 255;
    int hw = t & 1023;
    int row = (bi << 10) + hw;
    int idx = g_idx[row];
    float e  = emb[(size_t)idx * D + c];
    float zp = z[t];
    float diff = __fadd_rn(e, -zp);
    out[ZQ_OFF + (size_t)t] = __fadd_rn(zp, diff);
    __shared__ double sd[256];
    sd[threadIdx.x] = (double)diff * (double)diff;
    __syncthreads();
    #pragma unroll
    for (int s = 128; s > 0; s >>= 1) {
        if (threadIdx.x < s) sd[threadIdx.x] += sd[threadIdx.x + s];
        __syncthreads();
    }
    if (threadIdx.x == 0) g_losspart[blockIdx.x] = sd[0];
}

__global__ void k_loss_final(float* __restrict__ out) {
    __shared__ double sd[1024];
    double s = 0.0;
    for (int i = threadIdx.x; i < 16384; i += 1024) s += g_losspart[i];
    sd[threadIdx.x] = s;
    __syncthreads();
    #pragma unroll
    for (int st = 512; st > 0; st >>= 1) {
        if (threadIdx.x < st) sd[threadIdx.x] += sd[threadIdx.x + st];
        __syncthreads();
    }
    if (threadIdx.x == 0) {
        float m = (float)(sd[0] / 4194304.0);
        out[LOSS_OFF] = __fadd_rn(m, __fmul_rn(0.25f, m));
    }
}

__global__ void k_perp(float* __restrict__ out) {
    __shared__ double sd[1024];
    double s = 0.0;
    for (int j = threadIdx.x; j < NE; j += 1024) {
        float p = (float)g_count[j] * (1.0f / 16384.0f);
        double pd = (double)p;
        s += pd * log(pd + 1e-10);
    }
    sd[threadIdx.x] = s;
    __syncthreads();
    #pragma unroll
    for (int st = 512; st > 0; st >>= 1) {
        if (threadIdx.x < st) sd[threadIdx.x] += sd[threadIdx.x + st];
        __syncthreads();
    }
    if (threadIdx.x == 0) out[PERP_OFF] = (float)exp(-sd[0]);
}

// ---------------------------------------------------------------------------
extern "C" void kernel_launch(void* const* d_in, const int* in_sizes, int n_in,
                              void* d_out, int out_size) {
    const float* z   = (const float*)d_in[0];
    const float* emb = (const float*)d_in[1];
    float* out = (float*)d_out;

    static cudaStream_t s2 = nullptr;
    static cudaEvent_t evF = nullptr, evP = nullptr, evJ = nullptr;
    if (!s2) {
        cudaFuncSetAttribute(k_main, cudaFuncAttributeMaxDynamicSharedMemorySize, SMEM_BYTES);
        cudaStreamCreateWithFlags(&s2, cudaStreamNonBlocking);
        cudaEventCreateWithFlags(&evF, cudaEventDisableTiming);
        cudaEventCreateWithFlags(&evP, cudaEventDisableTiming);
        cudaEventCreateWithFlags(&evJ, cudaEventDisableTiming);
    }

    // Side stream: eprep first (k_main dependency), then the 1.07 GB zero-fill.
    cudaEventRecord(evF, 0);
    cudaStreamWaitEvent(s2, evF, 0);
    k_eprep<<<NE / 32, 256, 0, s2>>>(emb);
    cudaEventRecord(evP, s2);
    k_zero<<<8192, 256, 0, s2>>>(out, (long long)out_size);
    k_zero_counts<<<64, 256, 0, s2>>>();
    cudaEventRecord(evJ, s2);

    cudaStreamWaitEvent(0, evP, 0);     // g_ebf8 / g_enorm ready
    k_main<<<128, 256, SMEM_BYTES>>>(z, emb);

    cudaStreamWaitEvent(0, evJ, 0);     // zero-fill done before touching out[OH..]
    k_finalize<<<NROWS / 256, 256>>>(out);
    k_zq_loss<<<(NROWS * D) / 256, 256>>>(z, emb, out);
    k_loss_final<<<1, 1024>>>(out);
    k_perp<<<1, 1024>>>(out);
}

// round 12
// speedup vs baseline: 1.0437x; 1.0437x over previous
#include <cuda_runtime.h>
#include <cuda_bf16.h>
#include <math.h>
#include <stdint.h>

// Problem constants
#define NROWS 16384
#define NE    16384
#define D     256
#define HW    1024
#define CHW   262144

#define NT       128        // number of 128-code tiles
#define MARGIN_M 2e-4f      // margin on m_hat (provable bound ~9.6e-5)

// Output layout (concatenated reference tuple, float32)
#define ZQ_OFF   0ULL
#define LOSS_OFF 4194304ULL
#define PERP_OFF 4194305ULL
#define OH_OFF   4194306ULL
#define IDX_OFF  272629762ULL

// Scratch
__device__ float  g_enorm[NE];
__device__ float  g_znorm[NROWS];
__device__ int    g_idx[NROWS];
__device__ int    g_count[NE];
__device__ double g_losspart[16384];
__device__ uint4  g_ebf8[NE * 32];              // bf16 codebook, tile-major + swizzled (8 MB)
__device__ float  g_smax[(size_t)NROWS * 1024]; // per-row per-16-code-subtile max(m_hat)

// ---------------------------------------------------------------------------
// Baseline-PTX helpers (sm_90 features only)
// ---------------------------------------------------------------------------
__device__ __forceinline__ uint32_t smem_to_u32(const void* p) {
    uint32_t a;
    asm("{ .reg .u64 t; cvta.to.shared.u64 t, %1; cvt.u32.u64 %0, t; }" : "=r"(a) : "l"(p));
    return a;
}
#define MBARRIER_INIT(mb, cnt) \
    asm volatile("mbarrier.init.shared.b64 [%0], %1;" :: "r"((uint32_t)(mb)), "r"((uint32_t)(cnt)) : "memory")
#define MBARRIER_EXPECT_TX(mb, bytes) \
    asm volatile("mbarrier.arrive.expect_tx.shared.b64 _, [%0], %1;" :: "r"((uint32_t)(mb)), "r"((uint32_t)(bytes)) : "memory")
#define MBARRIER_WAIT_PARITY(mb, ph) do {                                          \
    uint32_t _m = (uint32_t)(mb); uint32_t _p = (uint32_t)(ph); uint32_t _d;       \
    asm volatile("{\n\t.reg .pred p;\n\t"                                          \
        "mbarrier.try_wait.parity.shared.b64 p, [%1], %2;\n\t"                     \
        "selp.b32 %0, 1, 0, p;\n\t}" : "=r"(_d) : "r"(_m), "r"(_p) : "memory");    \
    if (!_d) {                                                                     \
        asm volatile("{\n\t.reg .pred P1;\n\tWL_%=:\n\t"                           \
            "mbarrier.try_wait.parity.shared.b64 P1, [%0], %1;\n\t"                \
            "@P1 bra.uni WD_%=;\n\tbra.uni WL_%=;\n\tWD_%=:\n\t}"                  \
            :: "r"(_m), "r"(_p) : "memory");                                       \
    } } while (0)

__device__ __forceinline__ void bulk_g2s(uint32_t dst, const void* src, uint32_t bytes, uint32_t mbar) {
    asm volatile("cp.async.bulk.shared::cluster.global.mbarrier::complete_tx::bytes [%0], [%1], %2, [%3];"
                 :: "r"(dst), "l"(src), "r"(bytes), "r"(mbar) : "memory");
}
__device__ __forceinline__ void ldm_x4(uint32_t* r, uint32_t addr) {
    asm volatile("ldmatrix.sync.aligned.m8n8.x4.shared.b16 {%0,%1,%2,%3}, [%4];"
                 : "=r"(r[0]), "=r"(r[1]), "=r"(r[2]), "=r"(r[3]) : "r"(addr));
}
__device__ __forceinline__ void mma16816(float* c, const uint32_t* a, uint32_t b0, uint32_t b1) {
    asm volatile("mma.sync.aligned.m16n8k16.row.col.f32.bf16.bf16.f32 "
                 "{%0,%1,%2,%3}, {%4,%5,%6,%7}, {%8,%9}, {%0,%1,%2,%3};"
                 : "+f"(c[0]), "+f"(c[1]), "+f"(c[2]), "+f"(c[3])
                 : "r"(a[0]), "r"(a[1]), "r"(a[2]), "r"(a[3]), "r"(b0), "r"(b1));
}

// ---------------------------------------------------------------------------
// Zero-fill (side stream, overlapped with eprep+GEMM)
// ---------------------------------------------------------------------------
__global__ void k_zero(float* __restrict__ out, long long total) {
    float4* o4 = (float4*)(out + LOSS_OFF);
    long long n = total - (long long)LOSS_OFF;
    long long n4 = n / 4;
    long long i = (long long)blockIdx.x * blockDim.x + threadIdx.x;
    long long stride = (long long)gridDim.x * blockDim.x;
    float4 zz = make_float4(0.f, 0.f, 0.f, 0.f);
    for (long long p = i; p < n4; p += stride) o4[p] = zz;
    long long t0 = n4 * 4;
    if (i < n - t0) out[LOSS_OFF + t0 + i] = 0.f;
}

__global__ void k_zero_counts() {
    int i = blockIdx.x * blockDim.x + threadIdx.x;
    if (i < NE) g_count[i] = 0;
}

// ---------------------------------------------------------------------------
// Fused e-prep: exact sequential ||e||^2 + bf16 codebook tile-major swizzled
// ---------------------------------------------------------------------------
__global__ void k_eprep(const float* __restrict__ emb) {
    __shared__ float se[32 * 257];
    int r0 = blockIdx.x * 32;
    int tid = threadIdx.x;
    const float* src = emb + (size_t)r0 * D;
    #pragma unroll
    for (int l = 0; l < 32; l++) {
        int i = l * 256 + tid;
        se[(i >> 8) * 257 + (i & 255)] = src[i];
    }
    __syncthreads();
    #pragma unroll
    for (int l = 0; l < 4; l++) {
        int id = l * 256 + tid;              // chunk id: 32 rows x 32 chunks
        int r = id >> 5, c = id & 31;
        int j = r0 + r;
        int tile = j >> 7, n = j & 127;
        const float* s8 = se + r * 257 + c * 8;
        uint32_t w[4];
        #pragma unroll
        for (int q = 0; q < 4; q++) {
            __nv_bfloat16 h0 = __float2bfloat16_rn(s8[q * 2]);
            __nv_bfloat16 h1 = __float2bfloat16_rn(s8[q * 2 + 1]);
            w[q] = (uint32_t)*(unsigned short*)&h0 | ((uint32_t)*(unsigned short*)&h1 << 16);
        }
        g_ebf8[(size_t)tile * 4096 + n * 32 + (c ^ (n & 7))] =
            make_uint4(w[0], w[1], w[2], w[3]);
    }
    if (tid < 32) {
        float s = 0.f;
        const float* row = se + tid * 257;
        for (int k = 0; k < D; k++) s = __fadd_rn(s, __fmul_rn(row[k], row[k]));
        g_enorm[r0 + tid] = s;
    }
}

// ---------------------------------------------------------------------------
// Main bf16 mma.sync GEMM — single pass, bulk-DMA double buffer,
// 512 threads (16 warps, 4x4 grid, 32x32 warp tiles) + fused znorm.
// Per-(row, 16-code subtile) max(m_hat) -> g_smax.
// ---------------------------------------------------------------------------
#define A_OFF  0
#define B_OFF  65536
#define B_SZ   65536
#define ST_OFF (B_OFF + 2 * B_SZ)           // 196608: stmax[2][128][9] floats
#define MB_OFF (ST_OFF + 2 * 128 * 9 * 4)   // 205824
#define SMEM_BYTES (MB_OFF + 64)            // 205888

__launch_bounds__(512, 1)
__global__ void k_main(const float* __restrict__ z) {
    extern __shared__ char smem[];
    uint32_t sbase = smem_to_u32(smem);
    float* stmax = (float*)(smem + ST_OFF);
    uint32_t mb0 = sbase + MB_OFF, mb1 = sbase + MB_OFF + 8;

    int tid  = threadIdx.x;
    int lane = tid & 31;
    int wid  = tid >> 5;
    int wm = wid >> 2;      // 0..3
    int wn = wid & 3;       // 0..3
    int row0 = blockIdx.x * 128;
    int b0 = row0 >> 10;
    int hw0 = row0 & 1023;

    if (tid == 0) { MBARRIER_INIT(mb0, 1); MBARRIER_INIT(mb1, 1); }
    __syncthreads();
    if (tid == 0) {
        MBARRIER_EXPECT_TX(mb0, B_SZ);
        bulk_g2s(sbase + B_OFF, g_ebf8, B_SZ, mb0);
        MBARRIER_EXPECT_TX(mb1, B_SZ);
        bulk_g2s(sbase + B_OFF + B_SZ, g_ebf8 + 4096, B_SZ, mb1);
    }

    // ---- Stage A: z -> bf16 smem (swizzled) + exact sequential znorm ----
    if (tid < 128) {
        int m = tid;
        const float* zb = z + (size_t)b0 * CHW + hw0 + m;
        int mx7 = m & 7;
        float s = 0.f;
        #pragma unroll 4
        for (int c = 0; c < 32; c++) {
            float v[8];
            #pragma unroll
            for (int q = 0; q < 8; q++) v[q] = zb[(size_t)(c * 8 + q) * HW];
            #pragma unroll
            for (int q = 0; q < 8; q++) s = __fadd_rn(s, __fmul_rn(v[q], v[q]));
            uint32_t w[4];
            #pragma unroll
            for (int q = 0; q < 4; q++) {
                __nv_bfloat16 h0 = __float2bfloat16_rn(v[q * 2]);
                __nv_bfloat16 h1 = __float2bfloat16_rn(v[q * 2 + 1]);
                w[q] = (uint32_t)*(unsigned short*)&h0 | ((uint32_t)*(unsigned short*)&h1 << 16);
            }
            *(uint4*)(smem + A_OFF + m * 512 + ((c ^ mx7) << 4)) =
                make_uint4(w[0], w[1], w[2], w[3]);
        }
        g_znorm[row0 + m] = s;
    }
    __syncthreads();

    // =========================== GEMM main loop =============================
    #pragma unroll 1
    for (int t = 0; t < NT; t++) {
        int buf = t & 1;
        MBARRIER_WAIT_PARITY(buf ? mb1 : mb0, (t >> 1) & 1);

        float acc[2][4][4];
        #pragma unroll
        for (int mt = 0; mt < 2; mt++)
            #pragma unroll
            for (int nt = 0; nt < 4; nt++)
                #pragma unroll
                for (int rr = 0; rr < 4; rr++) acc[mt][nt][rr] = 0.f;

        int rA = wm * 32 + (lane & 15);
        int rB = wn * 32 + (lane & 15);
        int hi = lane >> 4;
        uint32_t bB = sbase + B_OFF + (uint32_t)buf * B_SZ;

        #pragma unroll
        for (int ks = 0; ks < 16; ks++) {
            int chunk = ks * 2 + hi;
            uint32_t ra[2][4], rb[2][4];
            #pragma unroll
            for (int mt = 0; mt < 2; mt++) {
                int r = rA + mt * 16;
                ldm_x4(ra[mt], sbase + A_OFF + (uint32_t)(r * 512 + ((chunk ^ (r & 7)) << 4)));
            }
            #pragma unroll
            for (int np = 0; np < 2; np++) {
                int r = rB + np * 16;
                ldm_x4(rb[np], bB + (uint32_t)(r * 512 + ((chunk ^ (r & 7)) << 4)));
            }
            #pragma unroll
            for (int mt = 0; mt < 2; mt++) {
                mma16816(acc[mt][0], ra[mt], rb[0][0], rb[0][2]);
                mma16816(acc[mt][1], ra[mt], rb[0][1], rb[0][3]);
                mma16816(acc[mt][2], ra[mt], rb[1][0], rb[1][2]);
                mma16816(acc[mt][3], ra[mt], rb[1][1], rb[1][3]);
            }
        }

        // ---- Epilogue: per-(row, 16-code subtile) max of m_hat ----
        float* stm = stmax + buf * (128 * 9);
        #pragma unroll
        for (int mt = 0; mt < 2; mt++) {
            int rl = wm * 32 + mt * 16 + (lane >> 2);
            #pragma unroll
            for (int sb = 0; sb < 2; sb++) {
                float m0 = fmaxf(fmaxf(acc[mt][sb*2][0], acc[mt][sb*2][1]),
                                 fmaxf(acc[mt][sb*2+1][0], acc[mt][sb*2+1][1]));
                float m1 = fmaxf(fmaxf(acc[mt][sb*2][2], acc[mt][sb*2][3]),
                                 fmaxf(acc[mt][sb*2+1][2], acc[mt][sb*2+1][3]));
                m0 = fmaxf(m0, __shfl_xor_sync(0xffffffffu, m0, 1));
                m0 = fmaxf(m0, __shfl_xor_sync(0xffffffffu, m0, 2));
                m1 = fmaxf(m1, __shfl_xor_sync(0xffffffffu, m1, 1));
                m1 = fmaxf(m1, __shfl_xor_sync(0xffffffffu, m1, 2));
                if ((lane & 3) == 0) {
                    stm[rl * 9 + wn * 2 + sb]       = m0;
                    stm[(rl + 8) * 9 + wn * 2 + sb] = m1;
                }
            }
        }
        __syncthreads();                     // epilogue written; MMA reads done
        if (tid < 128) {
            const float* s = stm + tid * 9;
            float4* d = (float4*)(g_smax + (size_t)(row0 + tid) * 1024 + t * 8);
            d[0] = make_float4(s[0], s[1], s[2], s[3]);
            d[1] = make_float4(s[4], s[5], s[6], s[7]);
        }
        if (tid == 0 && t + 2 < NT) {
            uint32_t mb = buf ? mb1 : mb0;
            MBARRIER_EXPECT_TX(mb, B_SZ);
            bulk_g2s(sbase + B_OFF + (uint32_t)buf * B_SZ,
                     g_ebf8 + (size_t)(t + 2) * 4096, B_SZ, mb);
        }
    }
}

// ---------------------------------------------------------------------------
// Exact rescore (separate kernel): warp per row, 4 warps/block.
// Scan 1024 subtile-16 maxima, flag within MARGIN_M of row max; exact
// sequential-fma chain (float4 loads) on the 16 codes of each flagged subtile.
// ---------------------------------------------------------------------------
__global__ void k_rescore(const float* __restrict__ z, const float* __restrict__ emb) {
    __shared__ float zs[4][256];
    __shared__ int flist[4][32];
    __shared__ int fcnt[4];
    int wp   = threadIdx.x >> 5;
    int lane = threadIdx.x & 31;
    int w = blockIdx.x * 4 + wp;

    int b = w >> 10, hw = w & 1023;
    const float* zr = z + (size_t)b * CHW + hw;
    #pragma unroll
    for (int c = lane; c < 256; c += 32) zs[wp][c] = zr[(size_t)c * HW];
    if (lane == 0) fcnt[wp] = 0;
    __syncwarp();

    const float4* sm4 = (const float4*)(g_smax + (size_t)w * 1024);
    float4 vv[8];
    float mx = -INFINITY;
    #pragma unroll
    for (int i = 0; i < 8; i++) {
        vv[i] = sm4[i * 32 + lane];
        mx = fmaxf(mx, fmaxf(fmaxf(vv[i].x, vv[i].y), fmaxf(vv[i].z, vv[i].w)));
    }
    #pragma unroll
    for (int o = 16; o; o >>= 1) mx = fmaxf(mx, __shfl_xor_sync(0xffffffffu, mx, o));
    float thr = mx - MARGIN_M;

    #pragma unroll
    for (int i = 0; i < 8; i++) {
        int sb = (i * 32 + lane) * 4;
        if (vv[i].x > thr) { int p = atomicAdd(&fcnt[wp], 1); if (p < 32) flist[wp][p] = sb; }
        if (vv[i].y > thr) { int p = atomicAdd(&fcnt[wp], 1); if (p < 32) flist[wp][p] = sb + 1; }
        if (vv[i].z > thr) { int p = atomicAdd(&fcnt[wp], 1); if (p < 32) flist[wp][p] = sb + 2; }
        if (vv[i].w > thr) { int p = atomicAdd(&fcnt[wp], 1); if (p < 32) flist[wp][p] = sb + 3; }
    }
    __syncwarp();
    int nf = fcnt[wp];

    float Sz = g_znorm[w];
    float bestd = INFINITY; int besti = 0x7fffffff;

    if (nf <= 32) {
        for (int base = 0; base < nf; base += 2) {
            int li = base + (lane >> 4);
            float dd = INFINITY; int code = 0x7fffffff;
            if (li < nf) {
                code = flist[wp][li] * 16 + (lane & 15);
                const float4* er = (const float4*)(emb + (size_t)code * D);
                float a = 0.f;
                #pragma unroll 16
                for (int q = 0; q < 64; q++) {
                    float4 ev = er[q];
                    a = fmaf(zs[wp][q * 4],     ev.x, a);
                    a = fmaf(zs[wp][q * 4 + 1], ev.y, a);
                    a = fmaf(zs[wp][q * 4 + 2], ev.z, a);
                    a = fmaf(zs[wp][q * 4 + 3], ev.w, a);
                }
                dd = __fadd_rn(__fadd_rn(Sz, g_enorm[code]), __fmul_rn(-2.0f, a));
            }
            if (dd < bestd || (dd == bestd && code < besti)) { bestd = dd; besti = code; }
        }
    } else {
        const float* sm = g_smax + (size_t)w * 1024;
        for (int sb = 0; sb < 1024; sb += 2) {
            int s = sb + (lane >> 4);
            float dd = INFINITY; int code = 0x7fffffff;
            if (sm[s] > thr) {
                code = s * 16 + (lane & 15);
                const float4* er = (const float4*)(emb + (size_t)code * D);
                float a = 0.f;
                for (int q = 0; q < 64; q++) {
                    float4 ev = er[q];
                    a = fmaf(zs[wp][q * 4],     ev.x, a);
                    a = fmaf(zs[wp][q * 4 + 1], ev.y, a);
                    a = fmaf(zs[wp][q * 4 + 2], ev.z, a);
                    a = fmaf(zs[wp][q * 4 + 3], ev.w, a);
                }
                dd = __fadd_rn(__fadd_rn(Sz, g_enorm[code]), __fmul_rn(-2.0f, a));
            }
            if (dd < bestd || (dd == bestd && code < besti)) { bestd = dd; besti = code; }
        }
    }
    #pragma unroll
    for (int o = 16; o; o >>= 1) {
        float vo = __shfl_xor_sync(0xffffffffu, bestd, o);
        int io = __shfl_xor_sync(0xffffffffu, besti, o);
        if (vo < bestd || (vo == bestd && io < besti)) { bestd = vo; besti = io; }
    }
    if (lane == 0) g_idx[w] = besti;
}

// ---------------------------------------------------------------------------
__global__ void k_finalize(float* __restrict__ out) {
    int r = blockIdx.x * blockDim.x + threadIdx.x;
    if (r >= NROWS) return;
    int idx = g_idx[r];
    out[IDX_OFF + r] = (float)idx;
    out[OH_OFF + (size_t)r * NE + idx] = 1.0f;
    atomicAdd(&g_count[idx], 1);
}

__global__ void k_zq_loss(const float* __restrict__ z, const float* __restrict__ emb,
                          float* __restrict__ out) {
    int t = blockIdx.x * 256 + threadIdx.x;
    int bi = t >> 18;
    int c  = (t >> 10) & 255;
    int hw = t & 1023;
    int row = (bi << 10) + hw;
    int idx = g_idx[row];
    float e  = emb[(size_t)idx * D + c];
    float zp = z[t];
    float diff = __fadd_rn(e, -zp);
    out[ZQ_OFF + (size_t)t] = __fadd_rn(zp, diff);
    __shared__ double sd[256];
    sd[threadIdx.x] = (double)diff * (double)diff;
    __syncthreads();
    #pragma unroll
    for (int s = 128; s > 0; s >>= 1) {
        if (threadIdx.x < s) sd[threadIdx.x] += sd[threadIdx.x + s];
        __syncthreads();
    }
    if (threadIdx.x == 0) g_losspart[blockIdx.x] = sd[0];
}

__global__ void k_loss_final(float* __restrict__ out) {
    __shared__ double sd[1024];
    double s = 0.0;
    for (int i = threadIdx.x; i < 16384; i += 1024) s += g_losspart[i];
    sd[threadIdx.x] = s;
    __syncthreads();
    #pragma unroll
    for (int st = 512; st > 0; st >>= 1) {
        if (threadIdx.x < st) sd[threadIdx.x] += sd[threadIdx.x + st];
        __syncthreads();
    }
    if (threadIdx.x == 0) {
        float m = (float)(sd[0] / 4194304.0);
        out[LOSS_OFF] = __fadd_rn(m, __fmul_rn(0.25f, m));
    }
}

__global__ void k_perp(float* __restrict__ out) {
    __shared__ double sd[1024];
    double s = 0.0;
    for (int j = threadIdx.x; j < NE; j += 1024) {
        float p = (float)g_count[j] * (1.0f / 16384.0f);
        double pd = (double)p;
        s += pd * log(pd + 1e-10);
    }
    sd[threadIdx.x] = s;
    __syncthreads();
    #pragma unroll
    for (int st = 512; st > 0; st >>= 1) {
        if (threadIdx.x < st) sd[threadIdx.x] += sd[threadIdx.x + st];
        __syncthreads();
    }
    if (threadIdx.x == 0) out[PERP_OFF] = (float)exp(-sd[0]);
}

// ---------------------------------------------------------------------------
extern "C" void kernel_launch(void* const* d_in, const int* in_sizes, int n_in,
                              void* d_out, int out_size) {
    const float* z   = (const float*)d_in[0];
    const float* emb = (const float*)d_in[1];
    float* out = (float*)d_out;

    static cudaStream_t s2 = nullptr;
    static cudaEvent_t evF = nullptr, evJ = nullptr;
    if (!s2) {
        cudaFuncSetAttribute(k_main, cudaFuncAttributeMaxDynamicSharedMemorySize, SMEM_BYTES);
        cudaStreamCreateWithFlags(&s2, cudaStreamNonBlocking);
        cudaEventCreateWithFlags(&evF, cudaEventDisableTiming);
        cudaEventCreateWithFlags(&evJ, cudaEventDisableTiming);
    }

    // Side stream: 1.07 GB zero-fill + count reset, overlapped with everything.
    cudaEventRecord(evF, 0);
    cudaStreamWaitEvent(s2, evF, 0);
    k_zero<<<8192, 256, 0, s2>>>(out, (long long)out_size);
    k_zero_counts<<<64, 256, 0, s2>>>();
    cudaEventRecord(evJ, s2);

    // Main stream: prep -> GEMM -> rescore -> zq/loss (ZQ region is not zeroed)
    k_eprep<<<NE / 32, 256>>>(emb);
    k_main<<<128, 512, SMEM_BYTES>>>(z);
    k_rescore<<<NROWS / 4, 128>>>(z, emb);
    k_zq_loss<<<(NROWS * D) / 256, 256>>>(z, emb, out);
    k_loss_final<<<1, 1024>>>(out);

    cudaStreamWaitEvent(0, evJ, 0);     // zero-fill done before touching out[OH..]
    k_finalize<<<NROWS / 256, 256>>>(out);
    k_perp<<<1, 1024>>>(out);
}

// round 13
// speedup vs baseline: 1.0444x; 1.0007x over previous
#include <cuda_runtime.h>
#include <cuda_bf16.h>
#include <math.h>
#include <stdint.h>

// Problem constants
#define NROWS 16384
#define NE    16384
#define D     256
#define HW    1024
#define CHW   262144

#define NT       128        // number of 128-code tiles
#define MARGIN_M 2e-4f      // margin on m_hat (provable bound ~9.6e-5)

// Output layout (concatenated reference tuple, float32)
#define ZQ_OFF   0ULL
#define LOSS_OFF 4194304ULL
#define PERP_OFF 4194305ULL
#define OH_OFF   4194306ULL
#define OH_ALN   4194308ULL  // first 16B-aligned float index in OH region
#define IDX_OFF  272629762ULL

// Scratch
__device__ float  g_enorm[NE];
__device__ float  g_znorm[NROWS];
__device__ int    g_idx[NROWS];
__device__ int    g_count[NE];
__device__ double g_losspart[128];
__device__ uint4  g_ebf8[NE * 32];              // bf16 codebook, tile-major + swizzled (8 MB)
__device__ float  g_smax[(size_t)NROWS * 1024]; // per-row per-16-code-subtile max(m_hat)

// ---------------------------------------------------------------------------
// Baseline-PTX helpers (sm_90 features only)
// ---------------------------------------------------------------------------
__device__ __forceinline__ uint32_t smem_to_u32(const void* p) {
    uint32_t a;
    asm("{ .reg .u64 t; cvta.to.shared.u64 t, %1; cvt.u32.u64 %0, t; }" : "=r"(a) : "l"(p));
    return a;
}
#define MBARRIER_INIT(mb, cnt) \
    asm volatile("mbarrier.init.shared.b64 [%0], %1;" :: "r"((uint32_t)(mb)), "r"((uint32_t)(cnt)) : "memory")
#define MBARRIER_EXPECT_TX(mb, bytes) \
    asm volatile("mbarrier.arrive.expect_tx.shared.b64 _, [%0], %1;" :: "r"((uint32_t)(mb)), "r"((uint32_t)(bytes)) : "memory")
#define MBARRIER_WAIT_PARITY(mb, ph) do {                                          \
    uint32_t _m = (uint32_t)(mb); uint32_t _p = (uint32_t)(ph); uint32_t _d;       \
    asm volatile("{\n\t.reg .pred p;\n\t"                                          \
        "mbarrier.try_wait.parity.shared.b64 p, [%1], %2;\n\t"                     \
        "selp.b32 %0, 1, 0, p;\n\t}" : "=r"(_d) : "r"(_m), "r"(_p) : "memory");    \
    if (!_d) {                                                                     \
        asm volatile("{\n\t.reg .pred P1;\n\tWL_%=:\n\t"                           \
            "mbarrier.try_wait.parity.shared.b64 P1, [%0], %1;\n\t"                \
            "@P1 bra.uni WD_%=;\n\tbra.uni WL_%=;\n\tWD_%=:\n\t}"                  \
            :: "r"(_m), "r"(_p) : "memory");                                       \
    } } while (0)

__device__ __forceinline__ void bulk_g2s(uint32_t dst, const void* src, uint32_t bytes, uint32_t mbar) {
    asm volatile("cp.async.bulk.shared::cluster.global.mbarrier::complete_tx::bytes [%0], [%1], %2, [%3];"
                 :: "r"(dst), "l"(src), "r"(bytes), "r"(mbar) : "memory");
}
__device__ __forceinline__ void ldm_x4(uint32_t* r, uint32_t addr) {
    asm volatile("ldmatrix.sync.aligned.m8n8.x4.shared.b16 {%0,%1,%2,%3}, [%4];"
                 : "=r"(r[0]), "=r"(r[1]), "=r"(r[2]), "=r"(r[3]) : "r"(addr));
}
__device__ __forceinline__ void mma16816(float* c, const uint32_t* a, uint32_t b0, uint32_t b1) {
    asm volatile("mma.sync.aligned.m16n8k16.row.col.f32.bf16.bf16.f32 "
                 "{%0,%1,%2,%3}, {%4,%5,%6,%7}, {%8,%9}, {%0,%1,%2,%3};"
                 : "+f"(c[0]), "+f"(c[1]), "+f"(c[2]), "+f"(c[3])
                 : "r"(a[0]), "r"(a[1]), "r"(a[2]), "r"(a[3]), "r"(b0), "r"(b1));
}

// ---------------------------------------------------------------------------
__global__ void k_zero_counts() {
    int i = blockIdx.x * blockDim.x + threadIdx.x;
    if (i < NE) g_count[i] = 0;
}

// ---------------------------------------------------------------------------
// Fused e-prep: exact sequential ||e||^2 + bf16 codebook tile-major swizzled
// ---------------------------------------------------------------------------
__global__ void k_eprep(const float* __restrict__ emb) {
    __shared__ float se[32 * 257];
    int r0 = blockIdx.x * 32;
    int tid = threadIdx.x;
    const float* src = emb + (size_t)r0 * D;
    #pragma unroll
    for (int l = 0; l < 32; l++) {
        int i = l * 256 + tid;
        se[(i >> 8) * 257 + (i & 255)] = src[i];
    }
    __syncthreads();
    #pragma unroll
    for (int l = 0; l < 4; l++) {
        int id = l * 256 + tid;
        int r = id >> 5, c = id & 31;
        int j = r0 + r;
        int tile = j >> 7, n = j & 127;
        const float* s8 = se + r * 257 + c * 8;
        uint32_t w[4];
        #pragma unroll
        for (int q = 0; q < 4; q++) {
            __nv_bfloat16 h0 = __float2bfloat16_rn(s8[q * 2]);
            __nv_bfloat16 h1 = __float2bfloat16_rn(s8[q * 2 + 1]);
            w[q] = (uint32_t)*(unsigned short*)&h0 | ((uint32_t)*(unsigned short*)&h1 << 16);
        }
        g_ebf8[(size_t)tile * 4096 + n * 32 + (c ^ (n & 7))] =
            make_uint4(w[0], w[1], w[2], w[3]);
    }
    if (tid < 32) {
        float s = 0.f;
        const float* row = se + tid * 257;
        for (int k = 0; k < D; k++) s = __fadd_rn(s, __fmul_rn(row[k], row[k]));
        g_enorm[r0 + tid] = s;
    }
}

// ---------------------------------------------------------------------------
// Main bf16 mma.sync GEMM — 512 threads, 16 warps (4x4), bulk-DMA double
// buffer, fused znorm + FUSED ONE-HOT ZERO-FILL (64 KB per CTA per tile).
// ---------------------------------------------------------------------------
#define A_OFF  0
#define B_OFF  65536
#define B_SZ   65536
#define ST_OFF (B_OFF + 2 * B_SZ)           // 196608: stmax[2][128][9] floats
#define MB_OFF (ST_OFF + 2 * 128 * 9 * 4)   // 205824
#define SMEM_BYTES (MB_OFF + 64)            // 205888

__launch_bounds__(512, 1)
__global__ void k_main(const float* __restrict__ z, float* __restrict__ out) {
    extern __shared__ char smem[];
    uint32_t sbase = smem_to_u32(smem);
    float* stmax = (float*)(smem + ST_OFF);
    uint32_t mb0 = sbase + MB_OFF, mb1 = sbase + MB_OFF + 8;

    int tid  = threadIdx.x;
    int lane = tid & 31;
    int wid  = tid >> 5;
    int wm = wid >> 2;      // 0..3
    int wn = wid & 3;       // 0..3
    int row0 = blockIdx.x * 128;
    int b0 = row0 >> 10;
    int hw0 = row0 & 1023;

    if (tid == 0) { MBARRIER_INIT(mb0, 1); MBARRIER_INIT(mb1, 1); }
    __syncthreads();
    if (tid == 0) {
        MBARRIER_EXPECT_TX(mb0, B_SZ);
        bulk_g2s(sbase + B_OFF, g_ebf8, B_SZ, mb0);
        MBARRIER_EXPECT_TX(mb1, B_SZ);
        bulk_g2s(sbase + B_OFF + B_SZ, g_ebf8 + 4096, B_SZ, mb1);
    }
    if (blockIdx.x == 0 && tid == 0) {
        out[OH_OFF] = 0.f; out[OH_OFF + 1] = 0.f;   // unaligned head of OH region
    }

    // ---- Stage A: z -> bf16 smem (swizzled) + exact sequential znorm ----
    if (tid < 128) {
        int m = tid;
        const float* zb = z + (size_t)b0 * CHW + hw0 + m;
        int mx7 = m & 7;
        float s = 0.f;
        #pragma unroll 4
        for (int c = 0; c < 32; c++) {
            float v[8];
            #pragma unroll
            for (int q = 0; q < 8; q++) v[q] = zb[(size_t)(c * 8 + q) * HW];
            #pragma unroll
            for (int q = 0; q < 8; q++) s = __fadd_rn(s, __fmul_rn(v[q], v[q]));
            uint32_t w[4];
            #pragma unroll
            for (int q = 0; q < 4; q++) {
                __nv_bfloat16 h0 = __float2bfloat16_rn(v[q * 2]);
                __nv_bfloat16 h1 = __float2bfloat16_rn(v[q * 2 + 1]);
                w[q] = (uint32_t)*(unsigned short*)&h0 | ((uint32_t)*(unsigned short*)&h1 << 16);
            }
            *(uint4*)(smem + A_OFF + m * 512 + ((c ^ mx7) << 4)) =
                make_uint4(w[0], w[1], w[2], w[3]);
        }
        g_znorm[row0 + m] = s;
    }
    __syncthreads();

    const uint4 zz4 = make_uint4(0u, 0u, 0u, 0u);

    // =========================== GEMM main loop =============================
    #pragma unroll 1
    for (int t = 0; t < NT; t++) {
        int buf = t & 1;
        MBARRIER_WAIT_PARITY(buf ? mb1 : mb0, (t >> 1) & 1);

        // Fused zero-fill: 4096 uint4 = 64 KB of the one-hot region per tile.
        {
            uint4* zdst = (uint4*)(out + OH_ALN) + (((size_t)blockIdx.x) * NT + t) * 4096;
            #pragma unroll
            for (int q = 0; q < 8; q++) zdst[q * 512 + tid] = zz4;
        }

        float acc[2][4][4];
        #pragma unroll
        for (int mt = 0; mt < 2; mt++)
            #pragma unroll
            for (int nt = 0; nt < 4; nt++)
                #pragma unroll
                for (int rr = 0; rr < 4; rr++) acc[mt][nt][rr] = 0.f;

        int rA = wm * 32 + (lane & 15);
        int rB = wn * 32 + (lane & 15);
        int hi = lane >> 4;
        uint32_t bB = sbase + B_OFF + (uint32_t)buf * B_SZ;

        #pragma unroll
        for (int ks = 0; ks < 16; ks++) {
            int chunk = ks * 2 + hi;
            uint32_t ra[2][4], rb[2][4];
            #pragma unroll
            for (int mt = 0; mt < 2; mt++) {
                int r = rA + mt * 16;
                ldm_x4(ra[mt], sbase + A_OFF + (uint32_t)(r * 512 + ((chunk ^ (r & 7)) << 4)));
            }
            #pragma unroll
            for (int np = 0; np < 2; np++) {
                int r = rB + np * 16;
                ldm_x4(rb[np], bB + (uint32_t)(r * 512 + ((chunk ^ (r & 7)) << 4)));
            }
            #pragma unroll
            for (int mt = 0; mt < 2; mt++) {
                mma16816(acc[mt][0], ra[mt], rb[0][0], rb[0][2]);
                mma16816(acc[mt][1], ra[mt], rb[0][1], rb[0][3]);
                mma16816(acc[mt][2], ra[mt], rb[1][0], rb[1][2]);
                mma16816(acc[mt][3], ra[mt], rb[1][1], rb[1][3]);
            }
        }

        // ---- Epilogue: per-(row, 16-code subtile) max of m_hat ----
        float* stm = stmax + buf * (128 * 9);
        #pragma unroll
        for (int mt = 0; mt < 2; mt++) {
            int rl = wm * 32 + mt * 16 + (lane >> 2);
            #pragma unroll
            for (int sb = 0; sb < 2; sb++) {
                float m0 = fmaxf(fmaxf(acc[mt][sb*2][0], acc[mt][sb*2][1]),
                                 fmaxf(acc[mt][sb*2+1][0], acc[mt][sb*2+1][1]));
                float m1 = fmaxf(fmaxf(acc[mt][sb*2][2], acc[mt][sb*2][3]),
                                 fmaxf(acc[mt][sb*2+1][2], acc[mt][sb*2+1][3]));
                m0 = fmaxf(m0, __shfl_xor_sync(0xffffffffu, m0, 1));
                m0 = fmaxf(m0, __shfl_xor_sync(0xffffffffu, m0, 2));
                m1 = fmaxf(m1, __shfl_xor_sync(0xffffffffu, m1, 1));
                m1 = fmaxf(m1, __shfl_xor_sync(0xffffffffu, m1, 2));
                if ((lane & 3) == 0) {
                    stm[rl * 9 + wn * 2 + sb]       = m0;
                    stm[(rl + 8) * 9 + wn * 2 + sb] = m1;
                }
            }
        }
        __syncthreads();
        if (tid < 128) {
            const float* s = stm + tid * 9;
            float4* d = (float4*)(g_smax + (size_t)(row0 + tid) * 1024 + t * 8);
            d[0] = make_float4(s[0], s[1], s[2], s[3]);
            d[1] = make_float4(s[4], s[5], s[6], s[7]);
        }
        if (tid == 0 && t + 2 < NT) {
            uint32_t mb = buf ? mb1 : mb0;
            MBARRIER_EXPECT_TX(mb, B_SZ);
            bulk_g2s(sbase + B_OFF + (uint32_t)buf * B_SZ,
                     g_ebf8 + (size_t)(t + 2) * 4096, B_SZ, mb);
        }
    }
}

// ---------------------------------------------------------------------------
// Exact rescore: 256 CTAs x 256 threads (8 warps), 64 rows per CTA.
// z block staged coalesced into smem (pitch 260). Warp per row, 8 rows each:
// scan 1024 subtile-16 maxima, flag within MARGIN_M of max, exact sequential
// fma chain on the 16 codes of each flagged subtile.
// ---------------------------------------------------------------------------
#define RS_SMEM (64 * 260 * 4)

__global__ void k_rescore(const float* __restrict__ z, const float* __restrict__ emb) {
    extern __shared__ float zs[];            // [64][260]
    __shared__ int flist[8][32];
    __shared__ int fcnt[8];
    int tid = threadIdx.x;
    int lane = tid & 31;
    int wp = tid >> 5;
    int row0 = blockIdx.x * 64;
    int b = row0 >> 10, hw0 = row0 & 1023;
    const float* zsrc = z + (size_t)b * CHW + hw0;

    #pragma unroll 4
    for (int it = 0; it < 64; it++) {
        int id = it * 256 + tid;
        int c = id >> 6, h = id & 63;
        zs[h * 260 + c] = zsrc[(size_t)c * HW + h];
    }
    __syncthreads();

    #pragma unroll 1
    for (int rr = 0; rr < 8; rr++) {
        int row = wp * 8 + rr;
        int w = row0 + row;
        if (lane == 0) fcnt[wp] = 0;
        __syncwarp();

        const float4* sm4 = (const float4*)(g_smax + (size_t)w * 1024);
        float4 vv[8];
        float mx = -INFINITY;
        #pragma unroll
        for (int i = 0; i < 8; i++) {
            vv[i] = sm4[i * 32 + lane];
            mx = fmaxf(mx, fmaxf(fmaxf(vv[i].x, vv[i].y), fmaxf(vv[i].z, vv[i].w)));
        }
        #pragma unroll
        for (int o = 16; o; o >>= 1) mx = fmaxf(mx, __shfl_xor_sync(0xffffffffu, mx, o));
        float thr = mx - MARGIN_M;

        #pragma unroll
        for (int i = 0; i < 8; i++) {
            int sb = (i * 32 + lane) * 4;
            if (vv[i].x > thr) { int p = atomicAdd(&fcnt[wp], 1); if (p < 32) flist[wp][p] = sb; }
            if (vv[i].y > thr) { int p = atomicAdd(&fcnt[wp], 1); if (p < 32) flist[wp][p] = sb + 1; }
            if (vv[i].z > thr) { int p = atomicAdd(&fcnt[wp], 1); if (p < 32) flist[wp][p] = sb + 2; }
            if (vv[i].w > thr) { int p = atomicAdd(&fcnt[wp], 1); if (p < 32) flist[wp][p] = sb + 3; }
        }
        __syncwarp();
        int nf = fcnt[wp];

        float Sz = g_znorm[w];
        const float4* zrow4 = (const float4*)(zs + row * 260);
        float bestd = INFINITY; int besti = 0x7fffffff;

        if (nf <= 32) {
            for (int base = 0; base < nf; base += 2) {
                int li = base + (lane >> 4);
                float dd = INFINITY; int code = 0x7fffffff;
                if (li < nf) {
                    code = flist[wp][li] * 16 + (lane & 15);
                    const float4* er = (const float4*)(emb + (size_t)code * D);
                    float a = 0.f;
                    #pragma unroll 16
                    for (int q = 0; q < 64; q++) {
                        float4 ev = er[q];
                        float4 zv = zrow4[q];
                        a = fmaf(zv.x, ev.x, a);
                        a = fmaf(zv.y, ev.y, a);
                        a = fmaf(zv.z, ev.z, a);
                        a = fmaf(zv.w, ev.w, a);
                    }
                    dd = __fadd_rn(__fadd_rn(Sz, g_enorm[code]), __fmul_rn(-2.0f, a));
                }
                if (dd < bestd || (dd == bestd && code < besti)) { bestd = dd; besti = code; }
            }
        } else {
            // overflow (effectively impossible): exact streaming scan
            const float* sm = g_smax + (size_t)w * 1024;
            for (int sb = 0; sb < 1024; sb += 2) {
                int s = sb + (lane >> 4);
                float dd = INFINITY; int code = 0x7fffffff;
                if (sm[s] > thr) {
                    code = s * 16 + (lane & 15);
                    const float4* er = (const float4*)(emb + (size_t)code * D);
                    float a = 0.f;
                    for (int q = 0; q < 64; q++) {
                        float4 ev = er[q];
                        float4 zv = zrow4[q];
                        a = fmaf(zv.x, ev.x, a);
                        a = fmaf(zv.y, ev.y, a);
                        a = fmaf(zv.z, ev.z, a);
                        a = fmaf(zv.w, ev.w, a);
                    }
                    dd = __fadd_rn(__fadd_rn(Sz, g_enorm[code]), __fmul_rn(-2.0f, a));
                }
                if (dd < bestd || (dd == bestd && code < besti)) { bestd = dd; besti = code; }
            }
        }
        #pragma unroll
        for (int o = 16; o; o >>= 1) {
            float vo = __shfl_xor_sync(0xffffffffu, bestd, o);
            int io = __shfl_xor_sync(0xffffffffu, besti, o);
            if (vo < bestd || (vo == bestd && io < besti)) { bestd = vo; besti = io; }
        }
        if (lane == 0) g_idx[w] = besti;
    }
}

// ---------------------------------------------------------------------------
// zq + straight-through + loss partials: 128 CTAs x 256 threads, 128 rows/CTA.
// z staged coalesced; emb gathered row-per-warp coalesced; out written back
// coalesced from smem.
// ---------------------------------------------------------------------------
#define ZQ_SMEM (128 * 260 * 4)

__global__ void k_zq_loss(const float* __restrict__ z, const float* __restrict__ emb,
                          float* __restrict__ out) {
    extern __shared__ float zs[];            // [128][260]
    __shared__ double lsum[8];
    int tid = threadIdx.x;
    int lane = tid & 31;
    int wp = tid >> 5;
    int row0 = blockIdx.x * 128;
    int b = row0 >> 10, hw0 = row0 & 1023;
    const float* zsrc = z + (size_t)b * CHW + hw0;

    #pragma unroll 4
    for (int it = 0; it < 128; it++) {
        int id = it * 256 + tid;
        int c = id >> 7, h = id & 127;
        zs[h * 260 + c] = zsrc[(size_t)c * HW + h];
    }
    __syncthreads();

    double acc = 0.0;
    #pragma unroll 1
    for (int rr = 0; rr < 16; rr++) {
        int row = wp * 16 + rr;
        int idx = g_idx[row0 + row];
        const float4* er = (const float4*)(emb + (size_t)idx * D);
        float4* zrow = (float4*)(zs + row * 260);
        #pragma unroll
        for (int s = 0; s < 2; s++) {
            int c4 = lane + s * 32;
            float4 e4 = er[c4];
            float4 z4 = zrow[c4];
            float d0 = __fadd_rn(e4.x, -z4.x);
            float d1 = __fadd_rn(e4.y, -z4.y);
            float d2 = __fadd_rn(e4.z, -z4.z);
            float d3 = __fadd_rn(e4.w, -z4.w);
            zrow[c4] = make_float4(__fadd_rn(z4.x, d0), __fadd_rn(z4.y, d1),
                                   __fadd_rn(z4.z, d2), __fadd_rn(z4.w, d3));
            acc += (double)d0 * d0 + (double)d1 * d1
                 + (double)d2 * d2 + (double)d3 * d3;
        }
    }
    #pragma unroll
    for (int o = 16; o; o >>= 1) acc += __shfl_xor_sync(0xffffffffu, acc, o);
    if (lane == 0) lsum[wp] = acc;
    __syncthreads();
    if (tid == 0) {
        double s = 0.0;
        #pragma unroll
        for (int i = 0; i < 8; i++) s += lsum[i];
        g_losspart[blockIdx.x] = s;
    }

    // coalesced write-back of straight-through output
    float* odst = out + ZQ_OFF + (size_t)b * CHW + hw0;
    #pragma unroll 4
    for (int it = 0; it < 128; it++) {
        int id = it * 256 + tid;
        int c = id >> 7, h = id & 127;
        odst[(size_t)c * HW + h] = zs[h * 260 + c];
    }
}

__global__ void k_loss_final(float* __restrict__ out) {
    __shared__ double sd[128];
    int t = threadIdx.x;
    sd[t] = g_losspart[t];
    __syncthreads();
    #pragma unroll
    for (int st = 64; st > 0; st >>= 1) {
        if (t < st) sd[t] += sd[t + st];
        __syncthreads();
    }
    if (t == 0) {
        float m = (float)(sd[0] / 4194304.0);
        out[LOSS_OFF] = __fadd_rn(m, __fmul_rn(0.25f, m));
    }
}

// ---------------------------------------------------------------------------
__global__ void k_finalize(float* __restrict__ out) {
    int r = blockIdx.x * blockDim.x + threadIdx.x;
    if (r >= NROWS) return;
    int idx = g_idx[r];
    out[IDX_OFF + r] = (float)idx;
    out[OH_OFF + (size_t)r * NE + idx] = 1.0f;
    atomicAdd(&g_count[idx], 1);
}

__global__ void k_perp(float* __restrict__ out) {
    __shared__ double sd[1024];
    double s = 0.0;
    for (int j = threadIdx.x; j < NE; j += 1024) {
        float p = (float)g_count[j] * (1.0f / 16384.0f);
        double pd = (double)p;
        s += pd * log(pd + 1e-10);
    }
    sd[threadIdx.x] = s;
    __syncthreads();
    #pragma unroll
    for (int st = 512; st > 0; st >>= 1) {
        if (threadIdx.x < st) sd[threadIdx.x] += sd[threadIdx.x + st];
        __syncthreads();
    }
    if (threadIdx.x == 0) out[PERP_OFF] = (float)exp(-sd[0]);
}

// ---------------------------------------------------------------------------
extern "C" void kernel_launch(void* const* d_in, const int* in_sizes, int n_in,
                              void* d_out, int out_size) {
    const float* z   = (const float*)d_in[0];
    const float* emb = (const float*)d_in[1];
    float* out = (float*)d_out;

    static int configured = 0;
    if (!configured) {
        cudaFuncSetAttribute(k_main, cudaFuncAttributeMaxDynamicSharedMemorySize, SMEM_BYTES);
        cudaFuncSetAttribute(k_rescore, cudaFuncAttributeMaxDynamicSharedMemorySize, RS_SMEM);
        cudaFuncSetAttribute(k_zq_loss, cudaFuncAttributeMaxDynamicSharedMemorySize, ZQ_SMEM);
        configured = 1;
    }

    k_zero_counts<<<64, 256>>>();
    k_eprep<<<NE / 32, 256>>>(emb);
    k_main<<<128, 512, SMEM_BYTES>>>(z, out);          // GEMM + fused one-hot zeroing
    k_rescore<<<256, 256, RS_SMEM>>>(z, emb);
    k_zq_loss<<<128, 256, ZQ_SMEM>>>(z, emb, out);
    k_loss_final<<<1, 128>>>(out);
    k_finalize<<<NROWS / 256, 256>>>(out);
    k_perp<<<1, 1024>>>(out);
}